// round 9
// baseline (speedup 1.0000x reference)
#include <cuda_runtime.h>
#include <math.h>

#define BB 4
#define SS 1024
#define EE 512
#define HH 8
#define HD 64
#define EPSF 1e-7f
#define NROW (BB*SS)          // 4096
#define PSZ (BB*SS*EE)        // 2,097,152 floats per tensor

typedef unsigned long long ull;

// ---- f32x2 packed helpers (Blackwell FFMA2 — PTX-only path) ----
__device__ __forceinline__ ull ffma2(ull a, ull b, ull c){
  ull d; asm("fma.rn.f32x2 %0, %1, %2, %3;" : "=l"(d) : "l"(a), "l"(b), "l"(c)); return d;
}
__device__ __forceinline__ ull dup2(float x){
  ull d; asm("mov.b64 %0, {%1, %1};" : "=l"(d) : "f"(x)); return d;
}
__device__ __forceinline__ float2 unpack2(ull a){
  float2 r; asm("mov.b64 {%0, %1}, %2;" : "=f"(r.x), "=f"(r.y) : "l"(a)); return r;
}
__device__ __forceinline__ float hadd2(ull a){ float2 r = unpack2(a); return r.x + r.y; }
union F4U { float4 f; ulonglong2 u; };

// Scratch (device globals; no allocation)
__device__ float g_p[3*PSZ];          // pq, pk, pv after h_linear (projected)
__device__ float g_v[3*PSZ];          // pre-projection v = 2 zn asinh(u)
__device__ float g_vp[PSZ];           // lam_v * pv
__device__ float g_e[(size_t)BB*HH*SS*SS];  // attention weights e (134 MB)
__device__ float g_q2[BB*HH*SS];
__device__ float g_k2[BB*HH*SS];
__device__ float g_lm1[BB*HH*SS];     // lam_v - 1
__device__ float g_den[BB*HH*SS];     // sum_k e*(lam-1), built by attn1 atomics
__device__ float g_lam[3*NROW];       // per input row conformal factor
__device__ float g_zn[3][EE];
__device__ float g_ch[3][EE];
__device__ float g_sh[3][EE];

// ---------------------------------------------------------------------------
// Prep 1: per-column weight constants: zn = ||z[:,j]||, cosh(2r), sinh(2r)
// ---------------------------------------------------------------------------
__global__ void prep_w_kernel(const float* __restrict__ zq, const float* __restrict__ rq,
                              const float* __restrict__ zk, const float* __restrict__ rk,
                              const float* __restrict__ zv, const float* __restrict__ rv){
  const int t = blockIdx.x;
  const float* z = (t==0)?zq:((t==1)?zk:zv);
  const float* r = (t==0)?rq:((t==1)?rk:rv);
  const int j = threadIdx.x;
  float s = 0.f;
  #pragma unroll 8
  for(int n=0;n<EE;n++){ float a = z[n*EE+j]; s = fmaf(a,a,s); }
  float zn = fmaxf(sqrtf(s), EPSF);
  g_zn[t][j] = zn;
  float tr = 2.f * r[j];
  g_ch[t][j] = coshf(tr);
  g_sh[t][j] = sinhf(tr);
}

// ---------------------------------------------------------------------------
// Prep 2: lam per input row (one warp per row) + zero g_den (replay-safe)
// ---------------------------------------------------------------------------
__global__ void __launch_bounds__(256) prep_lam_kernel(
    const float* __restrict__ xq, const float* __restrict__ xk, const float* __restrict__ xv){
  const int t = blockIdx.y;
  if(t == 0){
    int idx = blockIdx.x*256 + threadIdx.x;   // 512*256 = 131072 >= 32768
    if(idx < BB*HH*SS) g_den[idx] = 0.f;
  }
  const float* __restrict__ x = (t==0)?xq:((t==1)?xk:xv);
  const int r = blockIdx.x*8 + (threadIdx.x>>5);
  const int lane = threadIdx.x & 31;
  const float4* row = (const float4*)(x + (size_t)r*EE);
  float s = 0.f;
  #pragma unroll
  for(int i=0;i<4;i++){
    float4 a = row[lane + 32*i];
    s = fmaf(a.x,a.x, fmaf(a.y,a.y, fmaf(a.z,a.z, fmaf(a.w,a.w, s))));
  }
  #pragma unroll
  for(int o=16;o>0;o>>=1) s += __shfl_xor_sync(0xffffffffu, s, o);
  if(lane==0) g_lam[t*NROW + r] = 2.f / fmaxf(1.f - s, EPSF);
}

// ---------------------------------------------------------------------------
// h_linear GEMM: v = 2*zn*asinh( lam*(x@z)/zn*cosh(2r) - (lam-1)*sinh(2r) )
// 64 rows x 128 cols per 128-thread block, 8x8 per-thread tile, FFMA2 packed
// along OUTPUT cols (acc count = outputs/2).
// ---------------------------------------------------------------------------
#define GR 64
#define GC 128
#define GK 32
__global__ void __launch_bounds__(128, 4) hgemm_kernel(
    const float* __restrict__ xq, const float* __restrict__ xk, const float* __restrict__ xv,
    const float* __restrict__ zq, const float* __restrict__ zk, const float* __restrict__ zv){
  __shared__ float4 xs4[GR*GK/4];   // 8 KB
  __shared__ float4 zs4[GK*GC/4];   // 16 KB
  const int t = blockIdx.z;
  const float* __restrict__ x = (t==0)?xq:((t==1)?xk:xv);
  const float* __restrict__ z = (t==0)?zq:((t==1)?zk:zv);
  const int r0 = blockIdx.x*GR, c0 = blockIdx.y*GC;
  const int tid = threadIdx.x;
  const int wy = tid>>4, wx = tid&15;

  ull accP[8][4];
  #pragma unroll
  for(int i=0;i<8;i++){
    #pragma unroll
    for(int j=0;j<4;j++) accP[i][j] = 0ull;
  }

  const float4* xg = (const float4*)x;
  const float4* zg = (const float4*)z;

  for(int k0=0;k0<EE;k0+=GK){
    __syncthreads();
    #pragma unroll
    for(int i=0;i<4;i++){
      int idx = tid + i*128; int row = idx>>3, kq = idx&7;
      xs4[idx] = xg[(size_t)(r0+row)*128 + (k0>>2) + kq];
    }
    #pragma unroll
    for(int i=0;i<8;i++){
      int idx = tid + i*128; int kk = idx>>5, cq = idx&31;
      zs4[idx] = zg[(size_t)(k0+kk)*128 + (c0>>2) + cq];
    }
    __syncthreads();
    #pragma unroll
    for(int kq=0;kq<8;kq++){
      float4 xf[8];
      #pragma unroll
      for(int i=0;i<8;i++) xf[i] = xs4[(wy*8+i)*8 + kq];
      #pragma unroll
      for(int kk=0;kk<4;kk++){
        F4U z0, z1;
        z0.f = zs4[(kq*4+kk)*32 + wx];
        z1.f = zs4[(kq*4+kk)*32 + 16 + wx];
        #pragma unroll
        for(int i=0;i<8;i++){
          float xsc = (kk==0)?xf[i].x:((kk==1)?xf[i].y:((kk==2)?xf[i].z:xf[i].w));
          ull xd = dup2(xsc);
          accP[i][0] = ffma2(xd, z0.u.x, accP[i][0]);
          accP[i][1] = ffma2(xd, z0.u.y, accP[i][1]);
          accP[i][2] = ffma2(xd, z1.u.x, accP[i][2]);
          accP[i][3] = ffma2(xd, z1.u.y, accP[i][3]);
        }
      }
    }
  }

  F4U znA, znB, chA, chB, shA, shB;
  znA.f = ((const float4*)g_zn[t])[(c0>>2)+wx];       znB.f = ((const float4*)g_zn[t])[(c0>>2)+16+wx];
  chA.f = ((const float4*)g_ch[t])[(c0>>2)+wx];       chB.f = ((const float4*)g_ch[t])[(c0>>2)+16+wx];
  shA.f = ((const float4*)g_sh[t])[(c0>>2)+wx];       shB.f = ((const float4*)g_sh[t])[(c0>>2)+16+wx];
  float* __restrict__ vout = g_v + (size_t)t*PSZ;
  #pragma unroll
  for(int i=0;i<8;i++){
    const int row = r0 + wy*8 + i;
    const float lam = g_lam[t*NROW + row];
    const float lm1 = lam - 1.f;
    #pragma unroll
    for(int g=0; g<2; g++){
      float2 a0 = unpack2(accP[i][2*g]);
      float2 a1 = unpack2(accP[i][2*g+1]);
      float4 zn4 = g? znB.f : znA.f;
      float4 ch4 = g? chB.f : chA.f;
      float4 sh4 = g? shB.f : shA.f;
      float4 o;
      o.x = 2.f*zn4.x*asinhf(lam*a0.x/zn4.x*ch4.x - lm1*sh4.x);
      o.y = 2.f*zn4.y*asinhf(lam*a0.y/zn4.y*ch4.y - lm1*sh4.y);
      o.z = 2.f*zn4.z*asinhf(lam*a1.x/zn4.z*ch4.z - lm1*sh4.z);
      o.w = 2.f*zn4.w*asinhf(lam*a1.y/zn4.w*ch4.w - lm1*sh4.w);
      *(float4*)(vout + (size_t)row*EE + c0 + 4*wx + 64*g) = o;
    }
  }
}

// ---------------------------------------------------------------------------
// Projection + per-head prep. One warp per row.
// ---------------------------------------------------------------------------
__global__ void __launch_bounds__(256) proj_kernel(){
  const int t = blockIdx.y;
  const int r = blockIdx.x*8 + (threadIdx.x>>5);
  const int lane = threadIdx.x & 31;
  const float4* vrow = (const float4*)(g_v + (size_t)t*PSZ + (size_t)r*EE);
  float4 vv[4]; float hs[4];
  #pragma unroll
  for(int i=0;i<4;i++){
    vv[i] = vrow[lane + 32*i];
    float p = fmaf(vv[i].x,vv[i].x, fmaf(vv[i].y,vv[i].y,
              fmaf(vv[i].z,vv[i].z, vv[i].w*vv[i].w)));
    p += __shfl_xor_sync(0xffffffffu, p, 8);
    p += __shfl_xor_sync(0xffffffffu, p, 4);
    p += __shfl_xor_sync(0xffffffffu, p, 2);
    p += __shfl_xor_sync(0xffffffffu, p, 1);
    hs[i] = p;
  }
  float tot = hs[0]+hs[1]+hs[2]+hs[3];
  float v2 = tot + __shfl_xor_sync(0xffffffffu, tot, 16);
  float scl = 1.f/(1.f + sqrtf(1.f + v2));
  float scl2 = scl*scl;

  float* __restrict__ pout = g_p + (size_t)t*PSZ + (size_t)r*EE;
  const int b = r >> 10, s = r & (SS-1);
  if(t < 2){
    #pragma unroll
    for(int i=0;i<4;i++){
      float4 o; o.x=vv[i].x*scl; o.y=vv[i].y*scl; o.z=vv[i].z*scl; o.w=vv[i].w*scl;
      ((float4*)pout)[lane + 32*i] = o;
      if((lane & 15) == 0){
        int h = (lane>>4) + 2*i;
        int idx = (b*HH + h)*SS + s;
        if(t==0) g_q2[idx] = hs[i]*scl2; else g_k2[idx] = hs[i]*scl2;
      }
    }
  } else {
    float* __restrict__ vpout = g_vp + (size_t)r*EE;
    #pragma unroll
    for(int i=0;i<4;i++){
      float pv2h = hs[i]*scl2;
      float lamv = 2.f / fmaxf(1.f - pv2h, EPSF);
      float4 o; o.x=vv[i].x*scl; o.y=vv[i].y*scl; o.z=vv[i].z*scl; o.w=vv[i].w*scl;
      ((float4*)pout)[lane + 32*i] = o;
      float4 w; w.x=o.x*lamv; w.y=o.y*lamv; w.z=o.z*lamv; w.w=o.w*lamv;
      ((float4*)vpout)[lane + 32*i] = w;
      if((lane & 15) == 0){
        int h = (lane>>4) + 2*i;
        g_lm1[(b*HH + h)*SS + s] = lamv - 1.f;
      }
    }
  }
}

// ---------------------------------------------------------------------------
// attn1: scores -> e (g_e) + den (g_den via RED.ADD).
// 256 threads, Q-tile 128 x K-tile 64, per-thread 8q x 4k.
// FFMA2 d-packed, acc = 32 pairs (64 regs) — no spills.
//   e = arg - sqrt(arg^2-1) = exp(-arccosh(arg)), arg = 1 + t2
// ---------------------------------------------------------------------------
#define SWZ(row, c4) ((((row)<<4)) | ((c4) ^ (((row)>>2)&15)))

__global__ void __launch_bounds__(256, 1) attn1_kernel(){
  extern __shared__ float sm[];
  float4* Qs = (float4*)sm;               // 128 x 16 f4 (32 KB)
  float4* Ks = (float4*)(sm + 128*64);    // 64 x 16 f4  (16 KB)

  const int qt = blockIdx.x, h = blockIdx.y, b = blockIdx.z;
  const int tid = threadIdx.x;
  const int ty = tid >> 4, tx = tid & 15;  // ty: 16 q-groups of 8, tx: 16 k-groups of 4
  const int q0 = qt * 128;
  const int bh = (b*HH + h)*SS;
  const float* __restrict__ pq = g_p;
  const float* __restrict__ pk = g_p + PSZ;

  #pragma unroll
  for(int i=0;i<8;i++){
    int idx = tid + i*256; int row = idx>>4, c4 = idx&15;
    Qs[SWZ(row, c4)] = *(const float4*)(pq + ((size_t)(b*SS+q0+row))*EE + h*HD + c4*4);
  }
  float q2r[8], riq[8];
  #pragma unroll
  for(int i=0;i<8;i++){
    q2r[i] = g_q2[bh + q0 + ty*8 + i];
    riq[i] = __fdividef(1.f, 1.f - q2r[i]);
  }
  float* __restrict__ eout = g_e + ((size_t)(b*HH + h))*SS*SS;

  for(int kt=0; kt<SS/64; kt++){
    const int k0 = kt*64;
    __syncthreads();
    #pragma unroll
    for(int i=0;i<4;i++){
      int idx = tid + i*256; int row = idx>>4, c4 = idx&15;
      Ks[SWZ(row, c4)] = *(const float4*)(pk + ((size_t)(b*SS+k0+row))*EE + h*HD + c4*4);
    }
    float k2r[4], rik[4], lm1r[4];
    #pragma unroll
    for(int j=0;j<4;j++){
      k2r[j]  = g_k2[bh + k0 + tx*4 + j];
      rik[j]  = __fdividef(1.f, 1.f - k2r[j]);
      lm1r[j] = g_lm1[bh + k0 + tx*4 + j];
    }
    __syncthreads();

    ull scP[8][4];
    #pragma unroll
    for(int i=0;i<8;i++){
      #pragma unroll
      for(int j=0;j<4;j++) scP[i][j] = 0ull;
    }
    #pragma unroll
    for(int kd4=0; kd4<16; kd4++){
      F4U qv[8], kv[4];
      #pragma unroll
      for(int i=0;i<8;i++) qv[i].f = Qs[SWZ(ty*8+i, kd4)];
      #pragma unroll
      for(int j=0;j<4;j++) kv[j].f = Ks[SWZ(tx*4+j, kd4)];
      #pragma unroll
      for(int i=0;i<8;i++){
        #pragma unroll
        for(int j=0;j<4;j++){
          scP[i][j] = ffma2(qv[i].u.x, kv[j].u.x, scP[i][j]);
          scP[i][j] = ffma2(qv[i].u.y, kv[j].u.y, scP[i][j]);
        }
      }
    }

    // elementwise e, partial den (reduced over the 16 tx lanes), store e
    #pragma unroll
    for(int i=0;i<8;i++){
      float q2 = q2r[i], ri = riq[i];
      float e4[4];
      #pragma unroll
      for(int j=0;j<4;j++){
        float sc = hadd2(scP[i][j]);
        float d2 = fmaxf(q2 + k2r[j] - 2.f*sc, 0.f);
        float t2 = 2.f * d2 * ri * rik[j];
        float s  = sqrtf(t2 * (t2 + 2.f));
        e4[j] = (1.f + t2) - s;
      }
      float dp = fmaf(e4[0], lm1r[0], fmaf(e4[1], lm1r[1],
                 fmaf(e4[2], lm1r[2], e4[3]*lm1r[3])));
      dp += __shfl_xor_sync(0xffffffffu, dp, 1);
      dp += __shfl_xor_sync(0xffffffffu, dp, 2);
      dp += __shfl_xor_sync(0xffffffffu, dp, 4);
      dp += __shfl_xor_sync(0xffffffffu, dp, 8);
      if((tid & 15) == 0) atomicAdd(&g_den[bh + q0 + ty*8 + i], dp);
      float4 a; a.x=e4[0]; a.y=e4[1]; a.z=e4[2]; a.w=e4[3];
      *(float4*)(eout + (size_t)(q0 + ty*8 + i)*SS + k0 + tx*4) = a;
    }
  }
}

// ---------------------------------------------------------------------------
// attn2: num = E @ Vp, epilogue (midpoint + half mobius mul).
// 256 threads, Q-tile 128, per-thread 8q x 4d, FFMA2 packed along d
// (numP = 16 pairs). den read from g_den. Norm reduced via 4 shuffles.
// ---------------------------------------------------------------------------
__global__ void __launch_bounds__(256) attn2_kernel(float* __restrict__ out){
  extern __shared__ float sm[];
  float4* Es = (float4*)sm;               // 128 x 16 f4 (32 KB)
  float4* Vs = (float4*)(sm + 128*64);    // 64 x 16 f4  (16 KB)

  const int qt = blockIdx.x, h = blockIdx.y, b = blockIdx.z;
  const int tid = threadIdx.x;
  const int ty = tid >> 4, tx = tid & 15;  // ty: 16 q-groups of 8, tx: 16 d-groups of 4
  const int q0 = qt * 128;
  const int bh = (b*HH + h)*SS;
  const float* __restrict__ esrc = g_e + ((size_t)(b*HH + h))*SS*SS;

  ull numP[8][2];
  #pragma unroll
  for(int i=0;i<8;i++){ numP[i][0]=0ull; numP[i][1]=0ull; }

  for(int kt=0; kt<SS/64; kt++){
    const int k0 = kt*64;
    __syncthreads();
    #pragma unroll
    for(int i=0;i<8;i++){
      int idx = tid + i*256; int row = idx>>4, c4 = idx&15;
      Es[SWZ(row, c4)] = *(const float4*)(esrc + (size_t)(q0+row)*SS + k0 + c4*4);
    }
    #pragma unroll
    for(int i=0;i<4;i++){
      int idx = tid + i*256; int row = idx>>4, c4 = idx&15;
      Vs[SWZ(row, c4)] = *(const float4*)(g_vp + ((size_t)(b*SS+k0+row))*EE + h*HD + c4*4);
    }
    __syncthreads();

    #pragma unroll
    for(int kk4=0; kk4<16; kk4++){
      F4U ev[8], vv[4];
      #pragma unroll
      for(int i=0;i<8;i++) ev[i].f = Es[SWZ(ty*8+i, kk4)];
      #pragma unroll
      for(int r=0;r<4;r++) vv[r].f = Vs[SWZ(kk4*4+r, tx)];
      #pragma unroll
      for(int i=0;i<8;i++){
        ull e0 = dup2(ev[i].f.x), e1 = dup2(ev[i].f.y);
        ull e2 = dup2(ev[i].f.z), e3 = dup2(ev[i].f.w);
        numP[i][0] = ffma2(e0, vv[0].u.x, numP[i][0]);
        numP[i][1] = ffma2(e0, vv[0].u.y, numP[i][1]);
        numP[i][0] = ffma2(e1, vv[1].u.x, numP[i][0]);
        numP[i][1] = ffma2(e1, vv[1].u.y, numP[i][1]);
        numP[i][0] = ffma2(e2, vv[2].u.x, numP[i][0]);
        numP[i][1] = ffma2(e2, vv[2].u.y, numP[i][1]);
        numP[i][0] = ffma2(e3, vv[3].u.x, numP[i][0]);
        numP[i][1] = ffma2(e3, vv[3].u.y, numP[i][1]);
      }
    }
  }

  // epilogue: per q-row, 4 d's per thread; norm over 64 d via 4 shuffles
  #pragma unroll
  for(int i=0;i<8;i++){
    float dq = g_den[bh + q0 + ty*8 + i];
    dq = (fabsf(dq) < EPSF) ? EPSF : dq;
    float rdq = 1.f/dq;
    float2 n0 = unpack2(numP[i][0]);
    float2 n1 = unpack2(numP[i][1]);
    float mb[4];
    mb[0]=n0.x*rdq; mb[1]=n0.y*rdq; mb[2]=n1.x*rdq; mb[3]=n1.y*rdq;
    float p = fmaf(mb[0],mb[0], fmaf(mb[1],mb[1],
              fmaf(mb[2],mb[2], mb[3]*mb[3])));
    p += __shfl_xor_sync(0xffffffffu, p, 1);
    p += __shfl_xor_sync(0xffffffffu, p, 2);
    p += __shfl_xor_sync(0xffffffffu, p, 4);
    p += __shfl_xor_sync(0xffffffffu, p, 8);   // ||m_bar||^2 over all 64 d
    float mn = fmaxf(sqrtf(p), EPSF);
    float tt = fminf(mn, 1.f - 1e-6f);
    float fac = tt / ((1.f + sqrtf(1.f - tt*tt)) * mn);  // tanh(.5*atanh(tt))/mn
    float4 o;
    o.x=mb[0]*fac; o.y=mb[1]*fac; o.z=mb[2]*fac; o.w=mb[3]*fac;
    *(float4*)(out + ((size_t)(b*SS + q0 + ty*8 + i))*EE + h*HD + tx*4) = o;
  }
}

// ---------------------------------------------------------------------------
extern "C" void kernel_launch(void* const* d_in, const int* in_sizes, int n_in,
                              void* d_out, int out_size){
  const float* q  = (const float*)d_in[0];
  const float* k  = (const float*)d_in[1];
  const float* v  = (const float*)d_in[2];
  const float* zq = (const float*)d_in[3];
  const float* rq = (const float*)d_in[4];
  const float* zk = (const float*)d_in[5];
  const float* rk = (const float*)d_in[6];
  const float* zv = (const float*)d_in[7];
  const float* rv = (const float*)d_in[8];
  float* out = (float*)d_out;

  prep_w_kernel<<<3, EE>>>(zq, rq, zk, rk, zv, rv);
  prep_lam_kernel<<<dim3(NROW/8, 3), 256>>>(q, k, v);
  hgemm_kernel<<<dim3(NROW/GR, EE/GC, 3), 128>>>(q, k, v, zq, zk, zv);
  proj_kernel<<<dim3(NROW/8, 3), 256>>>();
  attn1_kernel<<<dim3(SS/128, HH, BB), 256, (128*64 + 64*64)*sizeof(float)>>>();
  attn2_kernel<<<dim3(SS/128, HH, BB), 256, (128*64 + 64*64)*sizeof(float)>>>(out);
}

// round 13
// speedup vs baseline: 1.1558x; 1.1558x over previous
#include <cuda_runtime.h>
#include <math.h>

#define BB 4
#define SS 1024
#define EE 512
#define HH 8
#define HD 64
#define EPSF 1e-7f
#define NROW (BB*SS)          // 4096
#define PSZ (BB*SS*EE)        // 2,097,152 floats per tensor

typedef unsigned long long ull;

// ---- f32x2 packed helpers (Blackwell FFMA2 — PTX-only path) ----
__device__ __forceinline__ ull ffma2(ull a, ull b, ull c){
  ull d; asm("fma.rn.f32x2 %0, %1, %2, %3;" : "=l"(d) : "l"(a), "l"(b), "l"(c)); return d;
}
__device__ __forceinline__ ull dup2(float x){
  ull d; asm("mov.b64 %0, {%1, %1};" : "=l"(d) : "f"(x)); return d;
}
__device__ __forceinline__ float2 unpack2(ull a){
  float2 r; asm("mov.b64 {%0, %1}, %2;" : "=f"(r.x), "=f"(r.y) : "l"(a)); return r;
}
union F4U { float4 f; ulonglong2 u; };

// Scratch (device globals; no allocation)
__device__ float g_p[3*PSZ];          // pq, pk, pv after h_linear (projected)
__device__ float g_v[3*PSZ];          // pre-projection v = 2 zn asinh(u)
__device__ float g_vp[PSZ];           // lam_v * pv
__device__ float g_q2[BB*HH*SS];
__device__ float g_k2[BB*HH*SS];
__device__ float g_lm1[BB*HH*SS];     // lam_v - 1
__device__ float g_lam[3*NROW];       // per input row conformal factor
__device__ float g_zn[3][EE];
__device__ float g_ch[3][EE];
__device__ float g_sh[3][EE];

// ---------------------------------------------------------------------------
// Prep 1: per-column weight constants
// ---------------------------------------------------------------------------
__global__ void prep_w_kernel(const float* __restrict__ zq, const float* __restrict__ rq,
                              const float* __restrict__ zk, const float* __restrict__ rk,
                              const float* __restrict__ zv, const float* __restrict__ rv){
  const int t = blockIdx.x;
  const float* z = (t==0)?zq:((t==1)?zk:zv);
  const float* r = (t==0)?rq:((t==1)?rk:rv);
  const int j = threadIdx.x;
  float s = 0.f;
  #pragma unroll 8
  for(int n=0;n<EE;n++){ float a = z[n*EE+j]; s = fmaf(a,a,s); }
  float zn = fmaxf(sqrtf(s), EPSF);
  g_zn[t][j] = zn;
  float tr = 2.f * r[j];
  g_ch[t][j] = coshf(tr);
  g_sh[t][j] = sinhf(tr);
}

// ---------------------------------------------------------------------------
// Prep 2: lam per input row (one warp per row)
// ---------------------------------------------------------------------------
__global__ void __launch_bounds__(256) prep_lam_kernel(
    const float* __restrict__ xq, const float* __restrict__ xk, const float* __restrict__ xv){
  const int t = blockIdx.y;
  const float* __restrict__ x = (t==0)?xq:((t==1)?xk:xv);
  const int r = blockIdx.x*8 + (threadIdx.x>>5);
  const int lane = threadIdx.x & 31;
  const float4* row = (const float4*)(x + (size_t)r*EE);
  float s = 0.f;
  #pragma unroll
  for(int i=0;i<4;i++){
    float4 a = row[lane + 32*i];
    s = fmaf(a.x,a.x, fmaf(a.y,a.y, fmaf(a.z,a.z, fmaf(a.w,a.w, s))));
  }
  #pragma unroll
  for(int o=16;o>0;o>>=1) s += __shfl_xor_sync(0xffffffffu, s, o);
  if(lane==0) g_lam[t*NROW + r] = 2.f / fmaxf(1.f - s, EPSF);
}

// ---------------------------------------------------------------------------
// h_linear GEMM (unchanged from R9): 64x128 per 128-thread block, 8x8, FFMA2
// ---------------------------------------------------------------------------
#define GR 64
#define GC 128
#define GK 32
__global__ void __launch_bounds__(128, 4) hgemm_kernel(
    const float* __restrict__ xq, const float* __restrict__ xk, const float* __restrict__ xv,
    const float* __restrict__ zq, const float* __restrict__ zk, const float* __restrict__ zv){
  __shared__ float4 xs4[GR*GK/4];
  __shared__ float4 zs4[GK*GC/4];
  const int t = blockIdx.z;
  const float* __restrict__ x = (t==0)?xq:((t==1)?xk:xv);
  const float* __restrict__ z = (t==0)?zq:((t==1)?zk:zv);
  const int r0 = blockIdx.x*GR, c0 = blockIdx.y*GC;
  const int tid = threadIdx.x;
  const int wy = tid>>4, wx = tid&15;

  ull accP[8][4];
  #pragma unroll
  for(int i=0;i<8;i++){
    #pragma unroll
    for(int j=0;j<4;j++) accP[i][j] = 0ull;
  }

  const float4* xg = (const float4*)x;
  const float4* zg = (const float4*)z;

  for(int k0=0;k0<EE;k0+=GK){
    __syncthreads();
    #pragma unroll
    for(int i=0;i<4;i++){
      int idx = tid + i*128; int row = idx>>3, kq = idx&7;
      xs4[idx] = xg[(size_t)(r0+row)*128 + (k0>>2) + kq];
    }
    #pragma unroll
    for(int i=0;i<8;i++){
      int idx = tid + i*128; int kk = idx>>5, cq = idx&31;
      zs4[idx] = zg[(size_t)(k0+kk)*128 + (c0>>2) + cq];
    }
    __syncthreads();
    #pragma unroll
    for(int kq=0;kq<8;kq++){
      float4 xf[8];
      #pragma unroll
      for(int i=0;i<8;i++) xf[i] = xs4[(wy*8+i)*8 + kq];
      #pragma unroll
      for(int kk=0;kk<4;kk++){
        F4U z0, z1;
        z0.f = zs4[(kq*4+kk)*32 + wx];
        z1.f = zs4[(kq*4+kk)*32 + 16 + wx];
        #pragma unroll
        for(int i=0;i<8;i++){
          float xsc = (kk==0)?xf[i].x:((kk==1)?xf[i].y:((kk==2)?xf[i].z:xf[i].w));
          ull xd = dup2(xsc);
          accP[i][0] = ffma2(xd, z0.u.x, accP[i][0]);
          accP[i][1] = ffma2(xd, z0.u.y, accP[i][1]);
          accP[i][2] = ffma2(xd, z1.u.x, accP[i][2]);
          accP[i][3] = ffma2(xd, z1.u.y, accP[i][3]);
        }
      }
    }
  }

  F4U znA, znB, chA, chB, shA, shB;
  znA.f = ((const float4*)g_zn[t])[(c0>>2)+wx];       znB.f = ((const float4*)g_zn[t])[(c0>>2)+16+wx];
  chA.f = ((const float4*)g_ch[t])[(c0>>2)+wx];       chB.f = ((const float4*)g_ch[t])[(c0>>2)+16+wx];
  shA.f = ((const float4*)g_sh[t])[(c0>>2)+wx];       shB.f = ((const float4*)g_sh[t])[(c0>>2)+16+wx];
  float* __restrict__ vout = g_v + (size_t)t*PSZ;
  #pragma unroll
  for(int i=0;i<8;i++){
    const int row = r0 + wy*8 + i;
    const float lam = g_lam[t*NROW + row];
    const float lm1 = lam - 1.f;
    #pragma unroll
    for(int g=0; g<2; g++){
      float2 a0 = unpack2(accP[i][2*g]);
      float2 a1 = unpack2(accP[i][2*g+1]);
      float4 zn4 = g? znB.f : znA.f;
      float4 ch4 = g? chB.f : chA.f;
      float4 sh4 = g? shB.f : shA.f;
      float4 o;
      o.x = 2.f*zn4.x*asinhf(lam*a0.x/zn4.x*ch4.x - lm1*sh4.x);
      o.y = 2.f*zn4.y*asinhf(lam*a0.y/zn4.y*ch4.y - lm1*sh4.y);
      o.z = 2.f*zn4.z*asinhf(lam*a1.x/zn4.z*ch4.z - lm1*sh4.z);
      o.w = 2.f*zn4.w*asinhf(lam*a1.y/zn4.w*ch4.w - lm1*sh4.w);
      *(float4*)(vout + (size_t)row*EE + c0 + 4*wx + 64*g) = o;
    }
  }
}

// ---------------------------------------------------------------------------
// Projection + per-head prep (unchanged from R9)
// ---------------------------------------------------------------------------
__global__ void __launch_bounds__(256) proj_kernel(){
  const int t = blockIdx.y;
  const int r = blockIdx.x*8 + (threadIdx.x>>5);
  const int lane = threadIdx.x & 31;
  const float4* vrow = (const float4*)(g_v + (size_t)t*PSZ + (size_t)r*EE);
  float4 vv[4]; float hs[4];
  #pragma unroll
  for(int i=0;i<4;i++){
    vv[i] = vrow[lane + 32*i];
    float p = fmaf(vv[i].x,vv[i].x, fmaf(vv[i].y,vv[i].y,
              fmaf(vv[i].z,vv[i].z, vv[i].w*vv[i].w)));
    p += __shfl_xor_sync(0xffffffffu, p, 8);
    p += __shfl_xor_sync(0xffffffffu, p, 4);
    p += __shfl_xor_sync(0xffffffffu, p, 2);
    p += __shfl_xor_sync(0xffffffffu, p, 1);
    hs[i] = p;
  }
  float tot = hs[0]+hs[1]+hs[2]+hs[3];
  float v2 = tot + __shfl_xor_sync(0xffffffffu, tot, 16);
  float scl = 1.f/(1.f + sqrtf(1.f + v2));
  float scl2 = scl*scl;

  float* __restrict__ pout = g_p + (size_t)t*PSZ + (size_t)r*EE;
  const int b = r >> 10, s = r & (SS-1);
  if(t < 2){
    #pragma unroll
    for(int i=0;i<4;i++){
      float4 o; o.x=vv[i].x*scl; o.y=vv[i].y*scl; o.z=vv[i].z*scl; o.w=vv[i].w*scl;
      ((float4*)pout)[lane + 32*i] = o;
      if((lane & 15) == 0){
        int h = (lane>>4) + 2*i;
        int idx = (b*HH + h)*SS + s;
        if(t==0) g_q2[idx] = hs[i]*scl2; else g_k2[idx] = hs[i]*scl2;
      }
    }
  } else {
    float* __restrict__ vpout = g_vp + (size_t)r*EE;
    #pragma unroll
    for(int i=0;i<4;i++){
      float pv2h = hs[i]*scl2;
      float lamv = 2.f / fmaxf(1.f - pv2h, EPSF);
      float4 o; o.x=vv[i].x*scl; o.y=vv[i].y*scl; o.z=vv[i].z*scl; o.w=vv[i].w*scl;
      ((float4*)pout)[lane + 32*i] = o;
      float4 w; w.x=o.x*lamv; w.y=o.y*lamv; w.z=o.z*lamv; w.w=o.w*lamv;
      ((float4*)vpout)[lane + 32*i] = w;
      if((lane & 15) == 0){
        int h = (lane>>4) + 2*i;
        g_lm1[(b*HH + h)*SS + s] = lamv - 1.f;
      }
    }
  }
}

// ---------------------------------------------------------------------------
// Fused attention v2: 128 threads, Q-tile 128, K-tile 64.
// ty = tid>>3 (16 q-groups of 8), tx = tid&7 (8 k-groups in G1 / 8 d-groups in G2).
// GEMM1 packs FFMA2 over q-PAIRS (Qt transposed in smem), K read as scalars
// (conflict-free via XOR-tx swizzle).  GEMM2 packs over d-pairs.
// Accumulators = outputs/2 in both GEMMs -> no register blowup.
// den accumulated in G1 from register-resident e + 3 shuffles.
// smem 96KB (opt-in), 2 blocks/SM, 1 wave of 256 blocks.
//
// Swizzle: logical (row, c4) -> f4 index row*16 + (c4 ^ ((row>>3)&7)).
// ---------------------------------------------------------------------------
#define SW3(row, c4) (((row)<<4) | ((c4) ^ (((row)>>3)&7)))

__global__ void __launch_bounds__(128) attn_kernel(float* __restrict__ out){
  extern __shared__ float sm[];
  float*  Qt  = sm;                    // [64 d][128 q] floats, no swizzle (32KB)
  float*  KsF = sm + 64*128;           // K tile, SW3 f4 layout (16KB)
  float*  VsF = sm + 64*128 + 64*64;   // V tile, SW3 f4 layout (16KB)
  float*  EsF = sm + 64*128 + 2*64*64; // E tile [128 q][64 k], SW3 (32KB)
  float4* Ks4 = (float4*)KsF;
  float4* Vs4 = (float4*)VsF;
  float4* Es4 = (float4*)EsF;

  const int qt = blockIdx.x, h = blockIdx.y, b = blockIdx.z;
  const int tid = threadIdx.x;
  const int ty = tid >> 3, tx = tid & 7;
  const int q0 = qt * 128;
  const int bh = (b*HH + h)*SS;
  const float* __restrict__ pq = g_p;
  const float* __restrict__ pk = g_p + PSZ;

  // ---- load Q transposed: Qt[d][q].  Lane owns one q-row (gather), 16 f4.
  {
    const float* qrow = pq + ((size_t)(b*SS + q0 + tid))*EE + h*HD;
    #pragma unroll
    for(int c4=0;c4<16;c4++){
      float4 v = *(const float4*)(qrow + c4*4);
      Qt[(c4*4+0)*128 + tid] = v.x;
      Qt[(c4*4+1)*128 + tid] = v.y;
      Qt[(c4*4+2)*128 + tid] = v.z;
      Qt[(c4*4+3)*128 + tid] = v.w;
    }
  }
  float q2r[8], riq2[8];
  #pragma unroll
  for(int i=0;i<8;i++){
    q2r[i]  = g_q2[bh + q0 + ty*8 + i];
    riq2[i] = 2.f * __fdividef(1.f, 1.f - q2r[i]);   // folds the 2* of t2
  }

  ull numP[8][4];          // 8 q-rows x 8 d (4 pairs)  = 64 regs
  float den[8];
  #pragma unroll
  for(int i=0;i<8;i++){
    den[i]=0.f;
    #pragma unroll
    for(int p=0;p<4;p++) numP[i][p]=0ull;
  }

  for(int kt=0; kt<SS/64; kt++){
    const int k0 = kt*64;
    __syncthreads();     // previous G2 reads complete
    // ---- load K, V tiles (SW3 f4 layout)
    #pragma unroll
    for(int i=0;i<8;i++){
      int idx = tid + i*128; int row = idx>>4, c4 = idx&15;
      Ks4[SW3(row,c4)] = *(const float4*)(pk   + ((size_t)(b*SS+k0+row))*EE + h*HD + c4*4);
      Vs4[SW3(row,c4)] = *(const float4*)(g_vp + ((size_t)(b*SS+k0+row))*EE + h*HD + c4*4);
    }
    float k2r[8], rik[8], lm1r[8];
    #pragma unroll
    for(int j=0;j<8;j++){
      k2r[j]  = g_k2[bh + k0 + tx*8 + j];
      rik[j]  = __fdividef(1.f, 1.f - k2r[j]);
      lm1r[j] = g_lm1[bh + k0 + tx*8 + j];
    }
    __syncthreads();

    // ---- GEMM1: scP[qp][j], packed over q-pairs.  q = ty*8 + qp*2 + {0,1}
    ull scP[4][8];
    #pragma unroll
    for(int qp=0;qp<4;qp++){
      #pragma unroll
      for(int j=0;j<8;j++) scP[qp][j] = 0ull;
    }
    #pragma unroll 4
    for(int kd=0; kd<64; kd++){
      F4U qa, qb;
      qa.f = *(const float4*)(Qt + kd*128 + ty*8);      // q pairs 0,1
      qb.f = *(const float4*)(Qt + kd*128 + ty*8 + 4);  // q pairs 2,3
      const int kc4 = kd>>2, klo = kd&3;
      #pragma unroll
      for(int j=0;j<8;j++){
        int krow = tx*8 + j;
        float kv = KsF[(krow<<6) | (((kc4 ^ tx)<<2) + klo)]; // (krow>>3)==tx
        ull kd2 = dup2(kv);
        scP[0][j] = ffma2(qa.u.x, kd2, scP[0][j]);
        scP[1][j] = ffma2(qa.u.y, kd2, scP[1][j]);
        scP[2][j] = ffma2(qb.u.x, kd2, scP[2][j]);
        scP[3][j] = ffma2(qb.u.y, kd2, scP[3][j]);
      }
    }

    // ---- e + den + store E tile.  e = (1+t2) - sqrt(t2(t2+2))
    #pragma unroll
    for(int qp=0;qp<4;qp++){
      float e0[8], e1[8];
      const int i0 = qp*2, i1 = qp*2+1;
      #pragma unroll
      for(int j=0;j<8;j++){
        float2 s = unpack2(scP[qp][j]);
        float d20 = fmaxf(fmaf(-2.f, s.x, q2r[i0] + k2r[j]), 0.f);
        float d21 = fmaxf(fmaf(-2.f, s.y, q2r[i1] + k2r[j]), 0.f);
        float t20 = d20 * riq2[i0] * rik[j];
        float t21 = d21 * riq2[i1] * rik[j];
        e0[j] = (1.f + t20) - sqrtf(t20*(t20 + 2.f));
        e1[j] = (1.f + t21) - sqrtf(t21*(t21 + 2.f));
      }
      float dp0 = 0.f, dp1 = 0.f;
      #pragma unroll
      for(int j=0;j<8;j++){ dp0 = fmaf(e0[j], lm1r[j], dp0); dp1 = fmaf(e1[j], lm1r[j], dp1); }
      dp0 += __shfl_xor_sync(0xffffffffu, dp0, 1);
      dp0 += __shfl_xor_sync(0xffffffffu, dp0, 2);
      dp0 += __shfl_xor_sync(0xffffffffu, dp0, 4);
      dp1 += __shfl_xor_sync(0xffffffffu, dp1, 1);
      dp1 += __shfl_xor_sync(0xffffffffu, dp1, 2);
      dp1 += __shfl_xor_sync(0xffffffffu, dp1, 4);
      den[i0] += dp0; den[i1] += dp1;
      const int q0r = ty*8 + i0, q1r = ty*8 + i1;
      float4 f; // logical c4 = tx*2, tx*2+1; (q>>3)==ty
      f.x=e0[0]; f.y=e0[1]; f.z=e0[2]; f.w=e0[3];
      Es4[(q0r<<4) | ((tx*2)   ^ ty)] = f;
      f.x=e0[4]; f.y=e0[5]; f.z=e0[6]; f.w=e0[7];
      Es4[(q0r<<4) | ((tx*2+1) ^ ty)] = f;
      f.x=e1[0]; f.y=e1[1]; f.z=e1[2]; f.w=e1[3];
      Es4[(q1r<<4) | ((tx*2)   ^ ty)] = f;
      f.x=e1[4]; f.y=e1[5]; f.z=e1[6]; f.w=e1[7];
      Es4[(q1r<<4) | ((tx*2+1) ^ ty)] = f;
    }
    __syncthreads();

    // ---- GEMM2: numP[i][p] += e[q][kk] * Vp[kk][d], d-pairs.
    // thread d's: {tx*4..tx*4+3} and {32+tx*4..32+tx*4+3}
    #pragma unroll 4
    for(int kk=0; kk<64; kk++){
      const int vc = (kk>>3)&7;
      F4U v0, v1;
      v0.f = Vs4[(kk<<4) | (tx ^ vc)];
      v1.f = Vs4[(kk<<4) | ((tx+8) ^ vc)];
      const int ec4 = kk>>2, elo = kk&3;
      #pragma unroll
      for(int i=0;i<8;i++){
        int qrow = ty*8 + i;                      // (qrow>>3)==ty
        float ev = EsF[(qrow<<6) | (((ec4 ^ ty)<<2) + elo)];
        ull ed = dup2(ev);
        numP[i][0] = ffma2(ed, v0.u.x, numP[i][0]);
        numP[i][1] = ffma2(ed, v0.u.y, numP[i][1]);
        numP[i][2] = ffma2(ed, v1.u.x, numP[i][2]);
        numP[i][3] = ffma2(ed, v1.u.y, numP[i][3]);
      }
    }
  }

  // ---- epilogue: all in registers + 3 shuffles per row
  #pragma unroll
  for(int i=0;i<8;i++){
    float dq = den[i];
    dq = (fabsf(dq) < EPSF) ? EPSF : dq;
    float rdq = 1.f/dq;
    float2 n0 = unpack2(numP[i][0]);
    float2 n1 = unpack2(numP[i][1]);
    float2 n2 = unpack2(numP[i][2]);
    float2 n3 = unpack2(numP[i][3]);
    float mb[8];
    mb[0]=n0.x*rdq; mb[1]=n0.y*rdq; mb[2]=n1.x*rdq; mb[3]=n1.y*rdq;
    mb[4]=n2.x*rdq; mb[5]=n2.y*rdq; mb[6]=n3.x*rdq; mb[7]=n3.y*rdq;
    float p = 0.f;
    #pragma unroll
    for(int j=0;j<8;j++) p = fmaf(mb[j], mb[j], p);
    p += __shfl_xor_sync(0xffffffffu, p, 1);
    p += __shfl_xor_sync(0xffffffffu, p, 2);
    p += __shfl_xor_sync(0xffffffffu, p, 4);   // ||m_bar||^2 over 64 d
    float mn = fmaxf(sqrtf(p), EPSF);
    float tt = fminf(mn, 1.f - 1e-6f);
    float fac = tt / ((1.f + sqrtf(1.f - tt*tt)) * mn);  // tanh(.5*atanh(tt))/mn
    float* orow = out + ((size_t)(b*SS + q0 + ty*8 + i))*EE + h*HD;
    float4 oa, ob;
    oa.x=mb[0]*fac; oa.y=mb[1]*fac; oa.z=mb[2]*fac; oa.w=mb[3]*fac;
    ob.x=mb[4]*fac; ob.y=mb[5]*fac; ob.z=mb[6]*fac; ob.w=mb[7]*fac;
    *(float4*)(orow + tx*4)      = oa;
    *(float4*)(orow + 32 + tx*4) = ob;
  }
}

// ---------------------------------------------------------------------------
extern "C" void kernel_launch(void* const* d_in, const int* in_sizes, int n_in,
                              void* d_out, int out_size){
  const float* q  = (const float*)d_in[0];
  const float* k  = (const float*)d_in[1];
  const float* v  = (const float*)d_in[2];
  const float* zq = (const float*)d_in[3];
  const float* rq = (const float*)d_in[4];
  const float* zk = (const float*)d_in[5];
  const float* rk = (const float*)d_in[6];
  const float* zv = (const float*)d_in[7];
  const float* rv = (const float*)d_in[8];
  float* out = (float*)d_out;

  const int ATTN_SMEM = (64*128 + 2*64*64 + 128*64) * sizeof(float);  // 96 KB
  cudaFuncSetAttribute(attn_kernel, cudaFuncAttributeMaxDynamicSharedMemorySize, ATTN_SMEM);

  prep_w_kernel<<<3, EE>>>(zq, rq, zk, rk, zv, rv);
  prep_lam_kernel<<<dim3(NROW/8, 3), 256>>>(q, k, v);
  hgemm_kernel<<<dim3(NROW/GR, EE/GC, 3), 128>>>(q, k, v, zq, zk, zv);
  proj_kernel<<<dim3(NROW/8, 3), 256>>>();
  attn_kernel<<<dim3(SS/128, HH, BB), 128, ATTN_SMEM>>>(out);
}

// round 16
// speedup vs baseline: 1.3369x; 1.1567x over previous
#include <cuda_runtime.h>
#include <math.h>
#include <stdint.h>

#define BB 4
#define SS 1024
#define EE 512
#define HH 8
#define HD 64
#define EPSF 1e-7f
#define NROW (BB*SS)          // 4096
#define PSZ (BB*SS*EE)        // 2,097,152 floats per tensor

typedef unsigned long long ull;

// ---- f32x2 packed helpers (Blackwell FFMA2 — PTX-only path) ----
__device__ __forceinline__ ull ffma2(ull a, ull b, ull c){
  ull d; asm("fma.rn.f32x2 %0, %1, %2, %3;" : "=l"(d) : "l"(a), "l"(b), "l"(c)); return d;
}
__device__ __forceinline__ ull dup2(float x){
  ull d; asm("mov.b64 %0, {%1, %1};" : "=l"(d) : "f"(x)); return d;
}
__device__ __forceinline__ float2 unpack2(ull a){
  float2 r; asm("mov.b64 {%0, %1}, %2;" : "=f"(r.x), "=f"(r.y) : "l"(a)); return r;
}
union F4U { float4 f; ulonglong2 u; };

// ---- TF32 helpers (portable PTX, works on compute_103 target) ----
__device__ __forceinline__ float tf32r(float x){
  uint32_t u; asm("cvt.rna.tf32.f32 %0, %1;" : "=r"(u) : "f"(x));
  return __uint_as_float(u);
}
__device__ __forceinline__ void mma_tf32(float* c, const uint32_t* a, uint32_t b0, uint32_t b1){
  asm("mma.sync.aligned.m16n8k8.row.col.f32.tf32.tf32.f32 "
      "{%0,%1,%2,%3}, {%4,%5,%6,%7}, {%8,%9}, {%0,%1,%2,%3};"
      : "+f"(c[0]), "+f"(c[1]), "+f"(c[2]), "+f"(c[3])
      : "r"(a[0]), "r"(a[1]), "r"(a[2]), "r"(a[3]), "r"(b0), "r"(b1));
}

// Scratch (device globals; no allocation)
__device__ float g_p[3*PSZ];          // pq, pk, pv after h_linear (projected)
__device__ float g_v[3*PSZ];          // pre-projection v = 2 zn asinh(u)
__device__ float g_vp[PSZ];           // lam_v * pv
__device__ float g_zt[3*EE*EE];       // z transposed: zt[n][k]
__device__ float g_q2[BB*HH*SS];
__device__ float g_k2[BB*HH*SS];
__device__ float g_lm1[BB*HH*SS];     // lam_v - 1
__device__ float g_lam[3*NROW];       // per input row conformal factor
__device__ float g_zn[3][EE];
__device__ float g_ch[3][EE];
__device__ float g_sh[3][EE];

// ---------------------------------------------------------------------------
// Prep 1: per-column weight constants
// ---------------------------------------------------------------------------
__global__ void prep_w_kernel(const float* __restrict__ zq, const float* __restrict__ rq,
                              const float* __restrict__ zk, const float* __restrict__ rk,
                              const float* __restrict__ zv, const float* __restrict__ rv){
  const int t = blockIdx.x;
  const float* z = (t==0)?zq:((t==1)?zk:zv);
  const float* r = (t==0)?rq:((t==1)?rk:rv);
  const int j = threadIdx.x;
  float s = 0.f;
  #pragma unroll 8
  for(int n=0;n<EE;n++){ float a = z[n*EE+j]; s = fmaf(a,a,s); }
  float zn = fmaxf(sqrtf(s), EPSF);
  g_zn[t][j] = zn;
  float tr = 2.f * r[j];
  g_ch[t][j] = coshf(tr);
  g_sh[t][j] = sinhf(tr);
}

// ---------------------------------------------------------------------------
// Prep 2: lam per input row (one warp per row)
// ---------------------------------------------------------------------------
__global__ void __launch_bounds__(256) prep_lam_kernel(
    const float* __restrict__ xq, const float* __restrict__ xk, const float* __restrict__ xv){
  const int t = blockIdx.y;
  const float* __restrict__ x = (t==0)?xq:((t==1)?xk:xv);
  const int r = blockIdx.x*8 + (threadIdx.x>>5);
  const int lane = threadIdx.x & 31;
  const float4* row = (const float4*)(x + (size_t)r*EE);
  float s = 0.f;
  #pragma unroll
  for(int i=0;i<4;i++){
    float4 a = row[lane + 32*i];
    s = fmaf(a.x,a.x, fmaf(a.y,a.y, fmaf(a.z,a.z, fmaf(a.w,a.w, s))));
  }
  #pragma unroll
  for(int o=16;o>0;o>>=1) s += __shfl_xor_sync(0xffffffffu, s, o);
  if(lane==0) g_lam[t*NROW + r] = 2.f / fmaxf(1.f - s, EPSF);
}

// ---------------------------------------------------------------------------
// Prep 3: transpose z -> zt[n][k] so the MMA B operand is K-major (col-major
// for mma's B = k x n view).
// ---------------------------------------------------------------------------
__global__ void __launch_bounds__(256) prep_zt_kernel(
    const float* __restrict__ zq, const float* __restrict__ zk, const float* __restrict__ zv){
  __shared__ float tb[32][33];
  const int t = blockIdx.z;
  const float* __restrict__ z = (t==0)?zq:((t==1)?zk:zv);
  float* __restrict__ zt = g_zt + (size_t)t*EE*EE;
  const int n0 = blockIdx.x*32, k0 = blockIdx.y*32;
  const int tx = threadIdx.x & 31, ty = threadIdx.x >> 5;
  #pragma unroll
  for(int i=0;i<32;i+=8) tb[ty+i][tx] = z[(size_t)(k0+ty+i)*EE + n0 + tx];
  __syncthreads();
  #pragma unroll
  for(int i=0;i<32;i+=8) zt[(size_t)(n0+ty+i)*EE + k0 + tx] = tb[tx][ty+i];
}

// ---------------------------------------------------------------------------
// h_linear GEMM on TF32 mma.sync (legacy HMMA path — portable PTX).
// Block: 128 rows x 64 cols, 4 warps; warp = 32 rows x 64 cols
//   = 2 m16-tiles x 8 n8-tiles, k8 steps.  K chunked at 32, single smem buf.
// Smem stride 36 floats -> fragment gathers hit all 32 banks (bank = 4g+c).
// tf32 rounding (cvt.rna) applied at the global->smem copy.
// ---------------------------------------------------------------------------
#define HKT 32
__global__ void __launch_bounds__(128) hgemm_mma_kernel(
    const float* __restrict__ xq, const float* __restrict__ xk, const float* __restrict__ xv){
  __shared__ float As[128][36];   // 18 KB
  __shared__ float Bs[64][36];    //  9 KB
  const int t = blockIdx.z;
  const float* __restrict__ x  = (t==0)?xq:((t==1)?xk:xv);
  const float* __restrict__ zt = g_zt + (size_t)t*EE*EE;
  const int r0 = blockIdx.x*128, c0 = blockIdx.y*64;
  const int tid = threadIdx.x, wid = tid>>5, lane = tid&31;
  const int g = lane>>2, c = lane&3;

  float acc[2][8][4];
  #pragma unroll
  for(int mt=0;mt<2;mt++)
    #pragma unroll
    for(int nt=0;nt<8;nt++)
      #pragma unroll
      for(int i=0;i<4;i++) acc[mt][nt][i] = 0.f;

  for(int k0=0;k0<EE;k0+=HKT){
    __syncthreads();
    // A: 128x32 floats = 1024 f4, 8 per thread (tf32-rounded on store)
    #pragma unroll
    for(int i=0;i<8;i++){
      int idx = tid + i*128; int row = idx>>3, c4 = idx&7;
      float4 a = *(const float4*)(x + (size_t)(r0+row)*EE + k0 + c4*4);
      float* d = &As[row][c4*4];
      d[0]=tf32r(a.x); d[1]=tf32r(a.y); d[2]=tf32r(a.z); d[3]=tf32r(a.w);
    }
    // B: 64x32 floats = 512 f4, 4 per thread
    #pragma unroll
    for(int i=0;i<4;i++){
      int idx = tid + i*128; int row = idx>>3, c4 = idx&7;
      float4 b = *(const float4*)(zt + (size_t)(c0+row)*EE + k0 + c4*4);
      float* d = &Bs[row][c4*4];
      d[0]=tf32r(b.x); d[1]=tf32r(b.y); d[2]=tf32r(b.z); d[3]=tf32r(b.w);
    }
    __syncthreads();

    #pragma unroll
    for(int s=0;s<4;s++){
      const int kb = s*8;
      uint32_t af[2][4];
      #pragma unroll
      for(int mt=0;mt<2;mt++){
        const int rb = wid*32 + mt*16;
        af[mt][0] = __float_as_uint(As[rb + g    ][kb + c    ]);
        af[mt][1] = __float_as_uint(As[rb + 8 + g][kb + c    ]);
        af[mt][2] = __float_as_uint(As[rb + g    ][kb + c + 4]);
        af[mt][3] = __float_as_uint(As[rb + 8 + g][kb + c + 4]);
      }
      #pragma unroll
      for(int nt=0;nt<8;nt++){
        uint32_t b0 = __float_as_uint(Bs[nt*8 + g][kb + c    ]);
        uint32_t b1 = __float_as_uint(Bs[nt*8 + g][kb + c + 4]);
        mma_tf32(acc[0][nt], af[0], b0, b1);
        mma_tf32(acc[1][nt], af[1], b0, b1);
      }
    }
  }

  // epilogue: thread owns rows {rb+g, rb+g+8} per m-tile, cols {2c, 2c+1} per n-tile
  float* __restrict__ vout = g_v + (size_t)t*PSZ;
  #pragma unroll
  for(int mt=0;mt<2;mt++){
    const int row0 = r0 + wid*32 + mt*16 + g;
    const int row1 = row0 + 8;
    const float lamA = g_lam[t*NROW + row0], lmA = lamA - 1.f;
    const float lamB = g_lam[t*NROW + row1], lmB = lamB - 1.f;
    #pragma unroll
    for(int nt=0;nt<8;nt++){
      const int col = c0 + nt*8 + 2*c;
      const float zn0 = g_zn[t][col],   ch0 = g_ch[t][col],   sh0 = g_sh[t][col];
      const float zn1 = g_zn[t][col+1], ch1 = g_ch[t][col+1], sh1 = g_sh[t][col+1];
      float2 oA, oB;
      oA.x = 2.f*zn0*asinhf(lamA*acc[mt][nt][0]/zn0*ch0 - lmA*sh0);
      oA.y = 2.f*zn1*asinhf(lamA*acc[mt][nt][1]/zn1*ch1 - lmA*sh1);
      oB.x = 2.f*zn0*asinhf(lamB*acc[mt][nt][2]/zn0*ch0 - lmB*sh0);
      oB.y = 2.f*zn1*asinhf(lamB*acc[mt][nt][3]/zn1*ch1 - lmB*sh1);
      *(float2*)(vout + (size_t)row0*EE + col) = oA;
      *(float2*)(vout + (size_t)row1*EE + col) = oB;
    }
  }
}

// ---------------------------------------------------------------------------
// Projection + per-head prep (unchanged)
// ---------------------------------------------------------------------------
__global__ void __launch_bounds__(256) proj_kernel(){
  const int t = blockIdx.y;
  const int r = blockIdx.x*8 + (threadIdx.x>>5);
  const int lane = threadIdx.x & 31;
  const float4* vrow = (const float4*)(g_v + (size_t)t*PSZ + (size_t)r*EE);
  float4 vv[4]; float hs[4];
  #pragma unroll
  for(int i=0;i<4;i++){
    vv[i] = vrow[lane + 32*i];
    float p = fmaf(vv[i].x,vv[i].x, fmaf(vv[i].y,vv[i].y,
              fmaf(vv[i].z,vv[i].z, vv[i].w*vv[i].w)));
    p += __shfl_xor_sync(0xffffffffu, p, 8);
    p += __shfl_xor_sync(0xffffffffu, p, 4);
    p += __shfl_xor_sync(0xffffffffu, p, 2);
    p += __shfl_xor_sync(0xffffffffu, p, 1);
    hs[i] = p;
  }
  float tot = hs[0]+hs[1]+hs[2]+hs[3];
  float v2 = tot + __shfl_xor_sync(0xffffffffu, tot, 16);
  float scl = 1.f/(1.f + sqrtf(1.f + v2));
  float scl2 = scl*scl;

  float* __restrict__ pout = g_p + (size_t)t*PSZ + (size_t)r*EE;
  const int b = r >> 10, s = r & (SS-1);
  if(t < 2){
    #pragma unroll
    for(int i=0;i<4;i++){
      float4 o; o.x=vv[i].x*scl; o.y=vv[i].y*scl; o.z=vv[i].z*scl; o.w=vv[i].w*scl;
      ((float4*)pout)[lane + 32*i] = o;
      if((lane & 15) == 0){
        int h = (lane>>4) + 2*i;
        int idx = (b*HH + h)*SS + s;
        if(t==0) g_q2[idx] = hs[i]*scl2; else g_k2[idx] = hs[i]*scl2;
      }
    }
  } else {
    float* __restrict__ vpout = g_vp + (size_t)r*EE;
    #pragma unroll
    for(int i=0;i<4;i++){
      float pv2h = hs[i]*scl2;
      float lamv = 2.f / fmaxf(1.f - pv2h, EPSF);
      float4 o; o.x=vv[i].x*scl; o.y=vv[i].y*scl; o.z=vv[i].z*scl; o.w=vv[i].w*scl;
      ((float4*)pout)[lane + 32*i] = o;
      float4 w; w.x=o.x*lamv; w.y=o.y*lamv; w.z=o.z*lamv; w.w=o.w*lamv;
      ((float4*)vpout)[lane + 32*i] = w;
      if((lane & 15) == 0){
        int h = (lane>>4) + 2*i;
        g_lm1[(b*HH + h)*SS + s] = lamv - 1.f;
      }
    }
  }
}

// ---------------------------------------------------------------------------
// Fused attention (unchanged winner from R13)
// ---------------------------------------------------------------------------
#define SW3(row, c4) (((row)<<4) | ((c4) ^ (((row)>>3)&7)))

__global__ void __launch_bounds__(128) attn_kernel(float* __restrict__ out){
  extern __shared__ float sm[];
  float*  Qt  = sm;
  float*  KsF = sm + 64*128;
  float*  VsF = sm + 64*128 + 64*64;
  float*  EsF = sm + 64*128 + 2*64*64;
  float4* Ks4 = (float4*)KsF;
  float4* Vs4 = (float4*)VsF;
  float4* Es4 = (float4*)EsF;

  const int qt = blockIdx.x, h = blockIdx.y, b = blockIdx.z;
  const int tid = threadIdx.x;
  const int ty = tid >> 3, tx = tid & 7;
  const int q0 = qt * 128;
  const int bh = (b*HH + h)*SS;
  const float* __restrict__ pq = g_p;
  const float* __restrict__ pk = g_p + PSZ;

  {
    const float* qrow = pq + ((size_t)(b*SS + q0 + tid))*EE + h*HD;
    #pragma unroll
    for(int c4=0;c4<16;c4++){
      float4 v = *(const float4*)(qrow + c4*4);
      Qt[(c4*4+0)*128 + tid] = v.x;
      Qt[(c4*4+1)*128 + tid] = v.y;
      Qt[(c4*4+2)*128 + tid] = v.z;
      Qt[(c4*4+3)*128 + tid] = v.w;
    }
  }
  float q2r[8], riq2[8];
  #pragma unroll
  for(int i=0;i<8;i++){
    q2r[i]  = g_q2[bh + q0 + ty*8 + i];
    riq2[i] = 2.f * __fdividef(1.f, 1.f - q2r[i]);
  }

  ull numP[8][4];
  float den[8];
  #pragma unroll
  for(int i=0;i<8;i++){
    den[i]=0.f;
    #pragma unroll
    for(int p=0;p<4;p++) numP[i][p]=0ull;
  }

  for(int kt=0; kt<SS/64; kt++){
    const int k0 = kt*64;
    __syncthreads();
    #pragma unroll
    for(int i=0;i<8;i++){
      int idx = tid + i*128; int row = idx>>4, c4 = idx&15;
      Ks4[SW3(row,c4)] = *(const float4*)(pk   + ((size_t)(b*SS+k0+row))*EE + h*HD + c4*4);
      Vs4[SW3(row,c4)] = *(const float4*)(g_vp + ((size_t)(b*SS+k0+row))*EE + h*HD + c4*4);
    }
    float k2r[8], rik[8], lm1r[8];
    #pragma unroll
    for(int j=0;j<8;j++){
      k2r[j]  = g_k2[bh + k0 + tx*8 + j];
      rik[j]  = __fdividef(1.f, 1.f - k2r[j]);
      lm1r[j] = g_lm1[bh + k0 + tx*8 + j];
    }
    __syncthreads();

    ull scP[4][8];
    #pragma unroll
    for(int qp=0;qp<4;qp++){
      #pragma unroll
      for(int j=0;j<8;j++) scP[qp][j] = 0ull;
    }
    #pragma unroll 4
    for(int kd=0; kd<64; kd++){
      F4U qa, qb;
      qa.f = *(const float4*)(Qt + kd*128 + ty*8);
      qb.f = *(const float4*)(Qt + kd*128 + ty*8 + 4);
      const int kc4 = kd>>2, klo = kd&3;
      #pragma unroll
      for(int j=0;j<8;j++){
        int krow = tx*8 + j;
        float kv = KsF[(krow<<6) | (((kc4 ^ tx)<<2) + klo)];
        ull kd2 = dup2(kv);
        scP[0][j] = ffma2(qa.u.x, kd2, scP[0][j]);
        scP[1][j] = ffma2(qa.u.y, kd2, scP[1][j]);
        scP[2][j] = ffma2(qb.u.x, kd2, scP[2][j]);
        scP[3][j] = ffma2(qb.u.y, kd2, scP[3][j]);
      }
    }

    #pragma unroll
    for(int qp=0;qp<4;qp++){
      float e0[8], e1[8];
      const int i0 = qp*2, i1 = qp*2+1;
      #pragma unroll
      for(int j=0;j<8;j++){
        float2 s = unpack2(scP[qp][j]);
        float d20 = fmaxf(fmaf(-2.f, s.x, q2r[i0] + k2r[j]), 0.f);
        float d21 = fmaxf(fmaf(-2.f, s.y, q2r[i1] + k2r[j]), 0.f);
        float t20 = d20 * riq2[i0] * rik[j];
        float t21 = d21 * riq2[i1] * rik[j];
        e0[j] = (1.f + t20) - sqrtf(t20*(t20 + 2.f));
        e1[j] = (1.f + t21) - sqrtf(t21*(t21 + 2.f));
      }
      float dp0 = 0.f, dp1 = 0.f;
      #pragma unroll
      for(int j=0;j<8;j++){ dp0 = fmaf(e0[j], lm1r[j], dp0); dp1 = fmaf(e1[j], lm1r[j], dp1); }
      dp0 += __shfl_xor_sync(0xffffffffu, dp0, 1);
      dp0 += __shfl_xor_sync(0xffffffffu, dp0, 2);
      dp0 += __shfl_xor_sync(0xffffffffu, dp0, 4);
      dp1 += __shfl_xor_sync(0xffffffffu, dp1, 1);
      dp1 += __shfl_xor_sync(0xffffffffu, dp1, 2);
      dp1 += __shfl_xor_sync(0xffffffffu, dp1, 4);
      den[i0] += dp0; den[i1] += dp1;
      const int q0r = ty*8 + i0, q1r = ty*8 + i1;
      float4 f;
      f.x=e0[0]; f.y=e0[1]; f.z=e0[2]; f.w=e0[3];
      Es4[(q0r<<4) | ((tx*2)   ^ ty)] = f;
      f.x=e0[4]; f.y=e0[5]; f.z=e0[6]; f.w=e0[7];
      Es4[(q0r<<4) | ((tx*2+1) ^ ty)] = f;
      f.x=e1[0]; f.y=e1[1]; f.z=e1[2]; f.w=e1[3];
      Es4[(q1r<<4) | ((tx*2)   ^ ty)] = f;
      f.x=e1[4]; f.y=e1[5]; f.z=e1[6]; f.w=e1[7];
      Es4[(q1r<<4) | ((tx*2+1) ^ ty)] = f;
    }
    __syncthreads();

    #pragma unroll 4
    for(int kk=0; kk<64; kk++){
      const int vc = (kk>>3)&7;
      F4U v0, v1;
      v0.f = Vs4[(kk<<4) | (tx ^ vc)];
      v1.f = Vs4[(kk<<4) | ((tx+8) ^ vc)];
      const int ec4 = kk>>2, elo = kk&3;
      #pragma unroll
      for(int i=0;i<8;i++){
        int qrow = ty*8 + i;
        float ev = EsF[(qrow<<6) | (((ec4 ^ ty)<<2) + elo)];
        ull ed = dup2(ev);
        numP[i][0] = ffma2(ed, v0.u.x, numP[i][0]);
        numP[i][1] = ffma2(ed, v0.u.y, numP[i][1]);
        numP[i][2] = ffma2(ed, v1.u.x, numP[i][2]);
        numP[i][3] = ffma2(ed, v1.u.y, numP[i][3]);
      }
    }
  }

  #pragma unroll
  for(int i=0;i<8;i++){
    float dq = den[i];
    dq = (fabsf(dq) < EPSF) ? EPSF : dq;
    float rdq = 1.f/dq;
    float2 n0 = unpack2(numP[i][0]);
    float2 n1 = unpack2(numP[i][1]);
    float2 n2 = unpack2(numP[i][2]);
    float2 n3 = unpack2(numP[i][3]);
    float mb[8];
    mb[0]=n0.x*rdq; mb[1]=n0.y*rdq; mb[2]=n1.x*rdq; mb[3]=n1.y*rdq;
    mb[4]=n2.x*rdq; mb[5]=n2.y*rdq; mb[6]=n3.x*rdq; mb[7]=n3.y*rdq;
    float p = 0.f;
    #pragma unroll
    for(int j=0;j<8;j++) p = fmaf(mb[j], mb[j], p);
    p += __shfl_xor_sync(0xffffffffu, p, 1);
    p += __shfl_xor_sync(0xffffffffu, p, 2);
    p += __shfl_xor_sync(0xffffffffu, p, 4);
    float mn = fmaxf(sqrtf(p), EPSF);
    float tt = fminf(mn, 1.f - 1e-6f);
    float fac = tt / ((1.f + sqrtf(1.f - tt*tt)) * mn);
    float* orow = out + ((size_t)(b*SS + q0 + ty*8 + i))*EE + h*HD;
    float4 oa, ob;
    oa.x=mb[0]*fac; oa.y=mb[1]*fac; oa.z=mb[2]*fac; oa.w=mb[3]*fac;
    ob.x=mb[4]*fac; ob.y=mb[5]*fac; ob.z=mb[6]*fac; ob.w=mb[7]*fac;
    *(float4*)(orow + tx*4)      = oa;
    *(float4*)(orow + 32 + tx*4) = ob;
  }
}

// ---------------------------------------------------------------------------
extern "C" void kernel_launch(void* const* d_in, const int* in_sizes, int n_in,
                              void* d_out, int out_size){
  const float* q  = (const float*)d_in[0];
  const float* k  = (const float*)d_in[1];
  const float* v  = (const float*)d_in[2];
  const float* zq = (const float*)d_in[3];
  const float* rq = (const float*)d_in[4];
  const float* zk = (const float*)d_in[5];
  const float* rk = (const float*)d_in[6];
  const float* zv = (const float*)d_in[7];
  const float* rv = (const float*)d_in[8];
  float* out = (float*)d_out;

  const int ATTN_SMEM = (64*128 + 2*64*64 + 128*64) * sizeof(float);  // 96 KB
  cudaFuncSetAttribute(attn_kernel, cudaFuncAttributeMaxDynamicSharedMemorySize, ATTN_SMEM);

  prep_w_kernel<<<3, EE>>>(zq, rq, zk, rk, zv, rv);
  prep_lam_kernel<<<dim3(NROW/8, 3), 256>>>(q, k, v);
  prep_zt_kernel<<<dim3(16, 16, 3), 256>>>(zq, zk, zv);
  hgemm_mma_kernel<<<dim3(NROW/128, EE/64, 3), 128>>>(q, k, v);
  proj_kernel<<<dim3(NROW/8, 3), 256>>>();
  attn_kernel<<<dim3(SS/128, HH, BB), 128, ATTN_SMEM>>>(out);
}